// round 15
// baseline (speedup 1.0000x reference)
#include <cuda_runtime.h>
#include <cuda_fp16.h>
#include <cuda_bf16.h>
#include <cstdint>

#define BATCH 2
#define SEQ   2048
#define DM    1024
#define NH    16
#define DH    64
#define MTOT  (BATCH*SEQ)   // 4096
#define NXF   (MTOT*DM)
#define NWF   (3*DM*DM)

__device__ __half g_Xh[NXF];
__device__ __half g_Wh[NWF];
__device__ __half g_Qh[MTOT*DM];   // [b,t,dm], pre-scaled by log2(e)/8
__device__ __half g_Kh[MTOT*DM];   // [b,t,dm]
__device__ __half g_Vt[MTOT*DM];   // [b, h*64+d, t] (transposed)

__device__ __forceinline__ void mma_f16_16x8x16(float* c, const uint32_t* a, uint32_t b0, uint32_t b1) {
    asm volatile(
        "mma.sync.aligned.m16n8k16.row.col.f32.f16.f16.f32 "
        "{%0,%1,%2,%3}, {%4,%5,%6,%7}, {%8,%9}, {%0,%1,%2,%3};"
        : "+f"(c[0]), "+f"(c[1]), "+f"(c[2]), "+f"(c[3])
        : "r"(a[0]), "r"(a[1]), "r"(a[2]), "r"(a[3]), "r"(b0), "r"(b1));
}

__device__ __forceinline__ void ldm_x4(uint32_t* r, uint32_t addr) {
    asm volatile("ldmatrix.sync.aligned.m8n8.x4.shared.b16 {%0,%1,%2,%3}, [%4];"
        : "=r"(r[0]), "=r"(r[1]), "=r"(r[2]), "=r"(r[3]) : "r"(addr));
}

__device__ __forceinline__ uint32_t pack_h2(float lo, float hi) {
    __half2 h = __floats2half2_rn(lo, hi);
    return *(uint32_t*)&h;
}

__device__ __forceinline__ uint32_t ex2_h2(uint32_t x) {
    uint32_t r;
    asm("ex2.approx.f16x2 %0, %1;" : "=r"(r) : "r"(x));
    return r;
}

__device__ __forceinline__ uint32_t smem_u32(const void* p) {
    return (uint32_t)__cvta_generic_to_shared(p);
}

__device__ __forceinline__ void cp16(uint32_t dst, const void* src) {
    asm volatile("cp.async.cg.shared.global [%0], [%1], 16;" :: "r"(dst), "l"(src));
}

// ---------------------------------------------------------------------------
// Prepass: X, Wq, Wk, Wv -> half.
// ---------------------------------------------------------------------------
__global__ __launch_bounds__(256) void cvt_half(
    const float* __restrict__ X,  const float* __restrict__ Wq,
    const float* __restrict__ Wk, const float* __restrict__ Wv)
{
    size_t i8 = ((size_t)blockIdx.x * 256 + threadIdx.x) * 8;
    const float* src;
    __half* dst;
    if (i8 < NXF) {
        src = X + i8;  dst = g_Xh + i8;
    } else {
        size_t j = i8 - NXF;
        size_t w = j / (DM * DM);
        size_t o = j - w * (DM * DM);
        src = ((w == 0) ? Wq : (w == 1) ? Wk : Wv) + o;
        dst = g_Wh + j;
    }
    float4 a = *(const float4*)src;
    float4 b = *(const float4*)(src + 4);
    uint4 o4;
    o4.x = pack_h2(a.x, a.y); o4.y = pack_h2(a.z, a.w);
    o4.z = pack_h2(b.x, b.y); o4.w = pack_h2(b.z, b.w);
    *(uint4*)dst = o4;
}

// ---------------------------------------------------------------------------
// QKV projection: fp16 mma + ldmatrix, 2-stage cp.async, occ=2  (R14 exact).
// ---------------------------------------------------------------------------
#define KC    32
#define XSTR  20
#define GROWB 80          // bytes per smem row
#define TSTR  136         // halves per transpose row

__global__ __launch_bounds__(256, 2) void qkv_gemm_h2()
{
    __shared__ __align__(16) char sbuf[40960];
    uint32_t (*Xs)[128][XSTR] = (uint32_t (*)[128][XSTR])sbuf;
    uint32_t (*Ws)[128][XSTR] = (uint32_t (*)[128][XSTR])(sbuf + 20480);

    const int z = blockIdx.z;
    const __half* Wsrc = g_Wh + (size_t)z * DM * DM;

    const int m0 = blockIdx.y * 128;
    const int n0 = blockIdx.x * 128;
    const int tid  = threadIdx.x;
    const int wid  = tid >> 5;
    const int lane = tid & 31;
    const int wm = wid >> 2;
    const int wn = wid & 3;
    const int g   = lane >> 2;
    const int tig = lane & 3;

    const int row_in = lane & 7;
    const int sel8   = (lane >> 3) & 1;
    const int sel16  = lane >> 4;

    const int qr  = tid >> 1;
    const int qcb = (tid & 1) * 32;

    const __half* xrow = &g_Xh[(size_t)(m0 + qr) * DM];
    const __half* wrow = &Wsrc[(size_t)(n0 + qr) * DM];

    {
        const char* xs = (const char*)(xrow) + qcb;
        uint32_t xd = smem_u32(&Xs[0][qr][0]) + qcb;
        cp16(xd, xs); cp16(xd + 16, xs + 16);
        const char* ws = (const char*)(wrow) + qcb;
        uint32_t wd = smem_u32(&Ws[0][qr][0]) + qcb;
        cp16(wd, ws); cp16(wd + 16, ws + 16);
        asm volatile("cp.async.commit_group;");
    }

    float acc[4][4][4] = {};

    const uint32_t xbase0 = smem_u32(&Xs[0][0][0]);
    const uint32_t wbase0 = smem_u32(&Ws[0][0][0]);

    for (int kc = 0; kc < DM / KC; kc++) {
        asm volatile("cp.async.wait_group 0;");
        __syncthreads();

        if (kc < DM / KC - 1) {
            const int bn = (kc + 1) & 1;
            const char* xs = (const char*)(xrow + (kc + 1) * KC) + qcb;
            uint32_t xd = smem_u32(&Xs[bn][qr][0]) + qcb;
            cp16(xd, xs); cp16(xd + 16, xs + 16);
            const char* ws = (const char*)(wrow + (kc + 1) * KC) + qcb;
            uint32_t wd = smem_u32(&Ws[bn][qr][0]) + qcb;
            cp16(wd, ws); cp16(wd + 16, ws + 16);
            asm volatile("cp.async.commit_group;");
        }

        const int bf = kc & 1;
        const uint32_t xb = xbase0 + (uint32_t)bf * 128 * GROWB;
        const uint32_t wb = wbase0 + (uint32_t)bf * 128 * GROWB;

        #pragma unroll
        for (int ks = 0; ks < 2; ks++) {
            const int kk = ks * 16;
            uint32_t a[4][4];
            #pragma unroll
            for (int mt = 0; mt < 4; mt++) {
                int r = wm * 64 + mt * 16 + row_in + sel8 * 8;
                int c = kk + sel16 * 8;
                ldm_x4(a[mt], xb + r * GROWB + c * 2);
            }
            uint32_t b[2][4];
            #pragma unroll
            for (int p = 0; p < 2; p++) {
                int r = wn * 32 + p * 16 + row_in + sel16 * 8;
                int c = kk + sel8 * 8;
                ldm_x4(b[p], wb + r * GROWB + c * 2);
            }
            #pragma unroll
            for (int mt = 0; mt < 4; mt++) {
                mma_f16_16x8x16(acc[mt][0], a[mt], b[0][0], b[0][1]);
                mma_f16_16x8x16(acc[mt][1], a[mt], b[0][2], b[0][3]);
                mma_f16_16x8x16(acc[mt][2], a[mt], b[1][0], b[1][1]);
                mma_f16_16x8x16(acc[mt][3], a[mt], b[1][2], b[1][3]);
            }
        }
    }

    if (z == 0) {
        const float s = 0.125f * 1.4426950408889634f;   // fold log2(e): exp2-domain softmax
        #pragma unroll
        for (int mt = 0; mt < 4; mt++) {
            int row = m0 + wm * 64 + mt * 16 + g;
            #pragma unroll
            for (int nt = 0; nt < 4; nt++) {
                int col = n0 + wn * 32 + nt * 8 + tig * 2;
                *(uint32_t*)&g_Qh[(size_t)row * DM + col] =
                    pack_h2(acc[mt][nt][0] * s, acc[mt][nt][1] * s);
                *(uint32_t*)&g_Qh[(size_t)(row + 8) * DM + col] =
                    pack_h2(acc[mt][nt][2] * s, acc[mt][nt][3] * s);
            }
        }
    } else if (z == 1) {
        #pragma unroll
        for (int mt = 0; mt < 4; mt++) {
            int row = m0 + wm * 64 + mt * 16 + g;
            #pragma unroll
            for (int nt = 0; nt < 4; nt++) {
                int col = n0 + wn * 32 + nt * 8 + tig * 2;
                *(uint32_t*)&g_Kh[(size_t)row * DM + col] =
                    pack_h2(acc[mt][nt][0], acc[mt][nt][1]);
                *(uint32_t*)&g_Kh[(size_t)(row + 8) * DM + col] =
                    pack_h2(acc[mt][nt][2], acc[mt][nt][3]);
            }
        }
    } else {
        __syncthreads();
        __half* Tr = (__half*)sbuf;      // [128 cols][TSTR]
        #pragma unroll
        for (int mt = 0; mt < 4; mt++) {
            int rl = wm * 64 + mt * 16 + g;
            #pragma unroll
            for (int nt = 0; nt < 4; nt++) {
                int cl = wn * 32 + nt * 8 + tig * 2;
                Tr[(cl    ) * TSTR + rl    ] = __float2half(acc[mt][nt][0]);
                Tr[(cl + 1) * TSTR + rl    ] = __float2half(acc[mt][nt][1]);
                Tr[(cl    ) * TSTR + rl + 8] = __float2half(acc[mt][nt][2]);
                Tr[(cl + 1) * TSTR + rl + 8] = __float2half(acc[mt][nt][3]);
            }
        }
        __syncthreads();
        const int bz = m0 >> 11;
        const int t0 = m0 & (SEQ - 1);
        const int cn  = tid >> 1;
        const int off = (tid & 1) * 64;
        __half* dst = &g_Vt[((size_t)bz * DM + n0 + cn) * SEQ + t0 + off];
        const __half* srow = &Tr[cn * TSTR + off];
        #pragma unroll
        for (int q = 0; q < 8; q++)
            *(uint4*)(dst + q * 8) = *(const uint4*)(srow + q * 8);
    }
}

// ---------------------------------------------------------------------------
// Tensor-core flash attention (R14 tile body) — unpaired, LPT scheduling:
// one Q-tile per CTA, heaviest (largest qt) first via qt = NQT-1-blockIdx.x.
// ---------------------------------------------------------------------------
#define HSTR  72
#define HROWB 144
#define NQT  (SEQ / 128)

__global__ __launch_bounds__(256, 2) void attn_tc(float* __restrict__ out)
{
    const int qt = NQT - 1 - blockIdx.x;   // LPT: heavy tiles launch first
    const int h  = blockIdx.y;
    const int b  = blockIdx.z;

    __shared__ __half Ks[2][64][HSTR];
    __shared__ __half Vt[2][64][HSTR];

    const int tid  = threadIdx.x;
    const int w    = tid >> 5;
    const int lane = tid & 31;
    const int g    = lane >> 2;
    const int tig  = lane & 3;
    const int row_in = lane & 7;
    const int sel8   = (lane >> 3) & 1;
    const int sel16  = lane >> 4;

    const __half* Qg = g_Qh + (size_t)b * SEQ * DM + h * DH;
    const __half* Kg = g_Kh + (size_t)b * SEQ * DM + h * DH;
    const __half* Vg = g_Vt + ((size_t)b * DM + h * DH) * SEQ;

    const int lr  = tid >> 2;
    const int lcb = (tid & 3) * 32;

    const uint32_t kbase0 = smem_u32(&Ks[0][0][0]);
    const uint32_t vbase0 = smem_u32(&Vt[0][0][0]);

    const int qb = qt * 128 + w * 16;

    uint32_t qf[4][4];
    #pragma unroll
    for (int ks = 0; ks < 4; ks++) {
        int c = ks * 16 + tig * 2;
        qf[ks][0] = *(const uint32_t*)&Qg[(size_t)(qb + g    ) * DM + c];
        qf[ks][1] = *(const uint32_t*)&Qg[(size_t)(qb + g + 8) * DM + c];
        qf[ks][2] = *(const uint32_t*)&Qg[(size_t)(qb + g    ) * DM + c + 8];
        qf[ks][3] = *(const uint32_t*)&Qg[(size_t)(qb + g + 8) * DM + c + 8];
    }

    float m0 = -1e30f, m1 = -1e30f, l0 = 0.0f, l1 = 0.0f;
    float O[8][4] = {};

    const int jmax = 2 * qt + 1;

    {
        const char* ksrc = (const char*)&Kg[(size_t)lr * DM] + lcb;
        uint32_t kdst = smem_u32(&Ks[0][lr][0]) + lcb;
        cp16(kdst, ksrc); cp16(kdst + 16, ksrc + 16);
        const char* vsrc = (const char*)&Vg[(size_t)lr * SEQ] + lcb;
        uint32_t vdst = smem_u32(&Vt[0][lr][0]) + lcb;
        cp16(vdst, vsrc); cp16(vdst + 16, vsrc + 16);
        asm volatile("cp.async.commit_group;");
    }

    for (int j = 0; j <= jmax; j++) {
        const int bf = j & 1;
        if (j < jmax) {
            const int jn = j + 1, bn = jn & 1;
            const char* ksrc = (const char*)&Kg[(size_t)(jn * 64 + lr) * DM] + lcb;
            uint32_t kdst = smem_u32(&Ks[bn][lr][0]) + lcb;
            cp16(kdst, ksrc); cp16(kdst + 16, ksrc + 16);
            const char* vsrc = (const char*)&Vg[(size_t)lr * SEQ + jn * 64] + lcb;
            uint32_t vdst = smem_u32(&Vt[bn][lr][0]) + lcb;
            cp16(vdst, vsrc); cp16(vdst + 16, vsrc + 16);
            asm volatile("cp.async.commit_group;");
            asm volatile("cp.async.wait_group 1;");
        } else {
            asm volatile("cp.async.wait_group 0;");
        }
        __syncthreads();

        if (j * 64 <= qb + 15) {
            const uint32_t kb = kbase0 + (uint32_t)bf * 64 * HROWB;
            const uint32_t vb = vbase0 + (uint32_t)bf * 64 * HROWB;

            float S[8][4] = {};
            #pragma unroll
            for (int ks = 0; ks < 4; ks++) {
                const int kk = ks * 16;
                #pragma unroll
                for (int p = 0; p < 4; p++) {
                    uint32_t kf[4];
                    int r = p * 16 + row_in + sel16 * 8;
                    int c = kk + sel8 * 8;
                    ldm_x4(kf, kb + r * HROWB + c * 2);
                    mma_f16_16x8x16(S[2*p    ], qf[ks], kf[0], kf[1]);
                    mma_f16_16x8x16(S[2*p + 1], qf[ks], kf[2], kf[3]);
                }
            }

            if (j >= 2 * qt) {
                #pragma unroll
                for (int nt = 0; nt < 8; nt++) {
                    int colb = j * 64 + nt * 8 + tig * 2;
                    int r0 = qb + g, r1 = qb + g + 8;
                    if (colb     > r0) S[nt][0] = -1e30f;
                    if (colb + 1 > r0) S[nt][1] = -1e30f;
                    if (colb     > r1) S[nt][2] = -1e30f;
                    if (colb + 1 > r1) S[nt][3] = -1e30f;
                }
            }

            float mx0 = -1e30f, mx1 = -1e30f;
            #pragma unroll
            for (int nt = 0; nt < 8; nt++) {
                mx0 = fmaxf(mx0, fmaxf(S[nt][0], S[nt][1]));
                mx1 = fmaxf(mx1, fmaxf(S[nt][2], S[nt][3]));
            }
            mx0 = fmaxf(mx0, __shfl_xor_sync(0xffffffffu, mx0, 1));
            mx0 = fmaxf(mx0, __shfl_xor_sync(0xffffffffu, mx0, 2));
            mx1 = fmaxf(mx1, __shfl_xor_sync(0xffffffffu, mx1, 1));
            mx1 = fmaxf(mx1, __shfl_xor_sync(0xffffffffu, mx1, 2));

            float mn0 = fmaxf(m0, mx0), mn1 = fmaxf(m1, mx1);
            float al0 = exp2f(m0 - mn0), al1 = exp2f(m1 - mn1);

            uint32_t Ph[8][2];
            float s0 = 0.0f, s1 = 0.0f;
            #pragma unroll
            for (int nt = 0; nt < 8; nt++) {
                Ph[nt][0] = ex2_h2(pack_h2(S[nt][0] - mn0, S[nt][1] - mn0));
                Ph[nt][1] = ex2_h2(pack_h2(S[nt][2] - mn1, S[nt][3] - mn1));
                float2 p0 = __half22float2(*(__half2*)&Ph[nt][0]);
                float2 p1 = __half22float2(*(__half2*)&Ph[nt][1]);
                s0 += p0.x + p0.y;
                s1 += p1.x + p1.y;
            }
            s0 += __shfl_xor_sync(0xffffffffu, s0, 1);
            s0 += __shfl_xor_sync(0xffffffffu, s0, 2);
            s1 += __shfl_xor_sync(0xffffffffu, s1, 1);
            s1 += __shfl_xor_sync(0xffffffffu, s1, 2);
            l0 = l0 * al0 + s0;  l1 = l1 * al1 + s1;
            m0 = mn0;            m1 = mn1;

            #pragma unroll
            for (int nt = 0; nt < 8; nt++) {
                O[nt][0] *= al0; O[nt][1] *= al0;
                O[nt][2] *= al1; O[nt][3] *= al1;
            }

            #pragma unroll
            for (int ks = 0; ks < 4; ks++) {
                uint32_t a[4];
                a[0] = Ph[2*ks    ][0];
                a[1] = Ph[2*ks    ][1];
                a[2] = Ph[2*ks + 1][0];
                a[3] = Ph[2*ks + 1][1];
                const int kk = ks * 16;
                #pragma unroll
                for (int p = 0; p < 4; p++) {
                    uint32_t vf[4];
                    int r = p * 16 + row_in + sel16 * 8;
                    int c = kk + sel8 * 8;
                    ldm_x4(vf, vb + r * HROWB + c * 2);
                    mma_f16_16x8x16(O[2*p    ], a, vf[0], vf[1]);
                    mma_f16_16x8x16(O[2*p + 1], a, vf[2], vf[3]);
                }
            }
        }
        __syncthreads();
    }

    float inv0 = 1.0f / l0, inv1 = 1.0f / l1;
    #pragma unroll
    for (int nt = 0; nt < 8; nt++) {
        int col = h * DH + nt * 8 + tig * 2;
        int r0 = qb + g, r1 = qb + g + 8;
        *(float2*)&out[(size_t)(b * SEQ + r0) * DM + col] =
            make_float2(O[nt][0] * inv0, O[nt][1] * inv0);
        *(float2*)&out[(size_t)(b * SEQ + r1) * DM + col] =
            make_float2(O[nt][2] * inv1, O[nt][3] * inv1);
    }
}

extern "C" void kernel_launch(void* const* d_in, const int* in_sizes, int n_in,
                              void* d_out, int out_size)
{
    const float* X  = (const float*)d_in[0];
    const float* Wq = (const float*)d_in[1];
    const float* Wk = (const float*)d_in[2];
    const float* Wv = (const float*)d_in[3];
    float* out = (float*)d_out;

    cvt_half<<<(NXF + NWF) / 8 / 256, 256>>>(X, Wq, Wk, Wv);

    dim3 ggrid(DM / 128, MTOT / 128, 3);
    qkv_gemm_h2<<<ggrid, 256>>>();

    dim3 agrid(NQT, NH, BATCH);
    attn_tc<<<agrid, 256>>>(out);
}

// round 16
// speedup vs baseline: 1.0984x; 1.0984x over previous
#include <cuda_runtime.h>
#include <cuda_fp16.h>
#include <cuda_bf16.h>
#include <cstdint>

#define BATCH 2
#define SEQ   2048
#define DM    1024
#define NH    16
#define DH    64
#define MTOT  (BATCH*SEQ)   // 4096
#define NXF   (MTOT*DM)
#define NWF   (3*DM*DM)

__device__ __half g_Xh[NXF];
__device__ __half g_Wh[NWF];
__device__ __half g_Qh[MTOT*DM];   // [b,t,dm], pre-scaled by log2(e)/8
__device__ __half g_Kh[MTOT*DM];   // [b,t,dm]
__device__ __half g_Vt[MTOT*DM];   // [b, h*64+d, t] (transposed)

__device__ __forceinline__ void mma_f16_16x8x16(float* c, const uint32_t* a, uint32_t b0, uint32_t b1) {
    asm volatile(
        "mma.sync.aligned.m16n8k16.row.col.f32.f16.f16.f32 "
        "{%0,%1,%2,%3}, {%4,%5,%6,%7}, {%8,%9}, {%0,%1,%2,%3};"
        : "+f"(c[0]), "+f"(c[1]), "+f"(c[2]), "+f"(c[3])
        : "r"(a[0]), "r"(a[1]), "r"(a[2]), "r"(a[3]), "r"(b0), "r"(b1));
}

__device__ __forceinline__ void ldm_x4(uint32_t* r, uint32_t addr) {
    asm volatile("ldmatrix.sync.aligned.m8n8.x4.shared.b16 {%0,%1,%2,%3}, [%4];"
        : "=r"(r[0]), "=r"(r[1]), "=r"(r[2]), "=r"(r[3]) : "r"(addr));
}

__device__ __forceinline__ uint32_t pack_h2(float lo, float hi) {
    __half2 h = __floats2half2_rn(lo, hi);
    return *(uint32_t*)&h;
}

__device__ __forceinline__ uint32_t ex2_h2(uint32_t x) {
    uint32_t r;
    asm("ex2.approx.f16x2 %0, %1;" : "=r"(r) : "r"(x));
    return r;
}

__device__ __forceinline__ uint32_t smem_u32(const void* p) {
    return (uint32_t)__cvta_generic_to_shared(p);
}

__device__ __forceinline__ void cp16(uint32_t dst, const void* src) {
    asm volatile("cp.async.cg.shared.global [%0], [%1], 16;" :: "r"(dst), "l"(src));
}

// ---------------------------------------------------------------------------
// Prepass: X, Wq, Wk, Wv -> half.
// ---------------------------------------------------------------------------
__global__ __launch_bounds__(256) void cvt_half(
    const float* __restrict__ X,  const float* __restrict__ Wq,
    const float* __restrict__ Wk, const float* __restrict__ Wv)
{
    size_t i8 = ((size_t)blockIdx.x * 256 + threadIdx.x) * 8;
    const float* src;
    __half* dst;
    if (i8 < NXF) {
        src = X + i8;  dst = g_Xh + i8;
    } else {
        size_t j = i8 - NXF;
        size_t w = j / (DM * DM);
        size_t o = j - w * (DM * DM);
        src = ((w == 0) ? Wq : (w == 1) ? Wk : Wv) + o;
        dst = g_Wh + j;
    }
    float4 a = *(const float4*)src;
    float4 b = *(const float4*)(src + 4);
    uint4 o4;
    o4.x = pack_h2(a.x, a.y); o4.y = pack_h2(a.z, a.w);
    o4.z = pack_h2(b.x, b.y); o4.w = pack_h2(b.z, b.w);
    *(uint4*)dst = o4;
}

// ---------------------------------------------------------------------------
// QKV projection: fp16 mma + ldmatrix, 2-stage cp.async, occ=2  (R14 exact).
// ---------------------------------------------------------------------------
#define KC    32
#define XSTR  20
#define GROWB 80          // bytes per smem row
#define TSTR  136         // halves per transpose row

__global__ __launch_bounds__(256, 2) void qkv_gemm_h2()
{
    __shared__ __align__(16) char sbuf[40960];
    uint32_t (*Xs)[128][XSTR] = (uint32_t (*)[128][XSTR])sbuf;
    uint32_t (*Ws)[128][XSTR] = (uint32_t (*)[128][XSTR])(sbuf + 20480);

    const int z = blockIdx.z;
    const __half* Wsrc = g_Wh + (size_t)z * DM * DM;

    const int m0 = blockIdx.y * 128;
    const int n0 = blockIdx.x * 128;
    const int tid  = threadIdx.x;
    const int wid  = tid >> 5;
    const int lane = tid & 31;
    const int wm = wid >> 2;
    const int wn = wid & 3;
    const int g   = lane >> 2;
    const int tig = lane & 3;

    const int row_in = lane & 7;
    const int sel8   = (lane >> 3) & 1;
    const int sel16  = lane >> 4;

    const int qr  = tid >> 1;
    const int qcb = (tid & 1) * 32;

    const __half* xrow = &g_Xh[(size_t)(m0 + qr) * DM];
    const __half* wrow = &Wsrc[(size_t)(n0 + qr) * DM];

    {
        const char* xs = (const char*)(xrow) + qcb;
        uint32_t xd = smem_u32(&Xs[0][qr][0]) + qcb;
        cp16(xd, xs); cp16(xd + 16, xs + 16);
        const char* ws = (const char*)(wrow) + qcb;
        uint32_t wd = smem_u32(&Ws[0][qr][0]) + qcb;
        cp16(wd, ws); cp16(wd + 16, ws + 16);
        asm volatile("cp.async.commit_group;");
    }

    float acc[4][4][4] = {};

    const uint32_t xbase0 = smem_u32(&Xs[0][0][0]);
    const uint32_t wbase0 = smem_u32(&Ws[0][0][0]);

    for (int kc = 0; kc < DM / KC; kc++) {
        asm volatile("cp.async.wait_group 0;");
        __syncthreads();

        if (kc < DM / KC - 1) {
            const int bn = (kc + 1) & 1;
            const char* xs = (const char*)(xrow + (kc + 1) * KC) + qcb;
            uint32_t xd = smem_u32(&Xs[bn][qr][0]) + qcb;
            cp16(xd, xs); cp16(xd + 16, xs + 16);
            const char* ws = (const char*)(wrow + (kc + 1) * KC) + qcb;
            uint32_t wd = smem_u32(&Ws[bn][qr][0]) + qcb;
            cp16(wd, ws); cp16(wd + 16, ws + 16);
            asm volatile("cp.async.commit_group;");
        }

        const int bf = kc & 1;
        const uint32_t xb = xbase0 + (uint32_t)bf * 128 * GROWB;
        const uint32_t wb = wbase0 + (uint32_t)bf * 128 * GROWB;

        #pragma unroll
        for (int ks = 0; ks < 2; ks++) {
            const int kk = ks * 16;
            uint32_t a[4][4];
            #pragma unroll
            for (int mt = 0; mt < 4; mt++) {
                int r = wm * 64 + mt * 16 + row_in + sel8 * 8;
                int c = kk + sel16 * 8;
                ldm_x4(a[mt], xb + r * GROWB + c * 2);
            }
            uint32_t b[2][4];
            #pragma unroll
            for (int p = 0; p < 2; p++) {
                int r = wn * 32 + p * 16 + row_in + sel16 * 8;
                int c = kk + sel8 * 8;
                ldm_x4(b[p], wb + r * GROWB + c * 2);
            }
            #pragma unroll
            for (int mt = 0; mt < 4; mt++) {
                mma_f16_16x8x16(acc[mt][0], a[mt], b[0][0], b[0][1]);
                mma_f16_16x8x16(acc[mt][1], a[mt], b[0][2], b[0][3]);
                mma_f16_16x8x16(acc[mt][2], a[mt], b[1][0], b[1][1]);
                mma_f16_16x8x16(acc[mt][3], a[mt], b[1][2], b[1][3]);
            }
        }
    }

    if (z == 0) {
        const float s = 0.125f * 1.4426950408889634f;   // fold log2(e): exp2-domain softmax
        #pragma unroll
        for (int mt = 0; mt < 4; mt++) {
            int row = m0 + wm * 64 + mt * 16 + g;
            #pragma unroll
            for (int nt = 0; nt < 4; nt++) {
                int col = n0 + wn * 32 + nt * 8 + tig * 2;
                *(uint32_t*)&g_Qh[(size_t)row * DM + col] =
                    pack_h2(acc[mt][nt][0] * s, acc[mt][nt][1] * s);
                *(uint32_t*)&g_Qh[(size_t)(row + 8) * DM + col] =
                    pack_h2(acc[mt][nt][2] * s, acc[mt][nt][3] * s);
            }
        }
    } else if (z == 1) {
        #pragma unroll
        for (int mt = 0; mt < 4; mt++) {
            int row = m0 + wm * 64 + mt * 16 + g;
            #pragma unroll
            for (int nt = 0; nt < 4; nt++) {
                int col = n0 + wn * 32 + nt * 8 + tig * 2;
                *(uint32_t*)&g_Kh[(size_t)row * DM + col] =
                    pack_h2(acc[mt][nt][0], acc[mt][nt][1]);
                *(uint32_t*)&g_Kh[(size_t)(row + 8) * DM + col] =
                    pack_h2(acc[mt][nt][2], acc[mt][nt][3]);
            }
        }
    } else {
        __syncthreads();
        __half* Tr = (__half*)sbuf;      // [128 cols][TSTR]
        #pragma unroll
        for (int mt = 0; mt < 4; mt++) {
            int rl = wm * 64 + mt * 16 + g;
            #pragma unroll
            for (int nt = 0; nt < 4; nt++) {
                int cl = wn * 32 + nt * 8 + tig * 2;
                Tr[(cl    ) * TSTR + rl    ] = __float2half(acc[mt][nt][0]);
                Tr[(cl + 1) * TSTR + rl    ] = __float2half(acc[mt][nt][1]);
                Tr[(cl    ) * TSTR + rl + 8] = __float2half(acc[mt][nt][2]);
                Tr[(cl + 1) * TSTR + rl + 8] = __float2half(acc[mt][nt][3]);
            }
        }
        __syncthreads();
        const int bz = m0 >> 11;
        const int t0 = m0 & (SEQ - 1);
        const int cn  = tid >> 1;
        const int off = (tid & 1) * 64;
        __half* dst = &g_Vt[((size_t)bz * DM + n0 + cn) * SEQ + t0 + off];
        const __half* srow = &Tr[cn * TSTR + off];
        #pragma unroll
        for (int q = 0; q < 8; q++)
            *(uint4*)(dst + q * 8) = *(const uint4*)(srow + q * 8);
    }
}

// ---------------------------------------------------------------------------
// Tensor-core flash attention (R14 tile body). Balanced 9-group schedule:
// per (b,h): group 0 = {15}; groups 1..7 = {15-g, g-1}; group 8 = {7}.
// Each of groups 0..7 = exactly 32 tile-units; group 8 = 16 (finishes early).
// Grid (9, NH, BATCH) = 288 CTAs -> one wave, makespan 32 vs 34 units.
// ---------------------------------------------------------------------------
#define HSTR  72
#define HROWB 144
#define NQT  (SEQ / 128)

__global__ __launch_bounds__(256, 2) void attn_tc(float* __restrict__ out)
{
    const int qa = blockIdx.x;   // 0..8
    const int h  = blockIdx.y;
    const int b  = blockIdx.z;

    __shared__ __half Ks[2][64][HSTR];
    __shared__ __half Vt[2][64][HSTR];

    const int tid  = threadIdx.x;
    const int w    = tid >> 5;
    const int lane = tid & 31;
    const int g    = lane >> 2;
    const int tig  = lane & 3;
    const int row_in = lane & 7;
    const int sel8   = (lane >> 3) & 1;
    const int sel16  = lane >> 4;

    const __half* Qg = g_Qh + (size_t)b * SEQ * DM + h * DH;
    const __half* Kg = g_Kh + (size_t)b * SEQ * DM + h * DH;
    const __half* Vg = g_Vt + ((size_t)b * DM + h * DH) * SEQ;

    const int lr  = tid >> 2;
    const int lcb = (tid & 3) * 32;

    const uint32_t kbase0 = smem_u32(&Ks[0][0][0]);
    const uint32_t vbase0 = smem_u32(&Vt[0][0][0]);

    // balanced groups: heavy tile first within each group
    int qts[2];
    int nq;
    if (qa == 0)      { qts[0] = 15;      nq = 1; }
    else if (qa == 8) { qts[0] = 7;       nq = 1; }
    else              { qts[0] = 15 - qa; qts[1] = qa - 1; nq = 2; }

    #pragma unroll 1
    for (int iq = 0; iq < nq; iq++) {
        const int qt = qts[iq];
        const int qb = qt * 128 + w * 16;

        uint32_t qf[4][4];
        #pragma unroll
        for (int ks = 0; ks < 4; ks++) {
            int c = ks * 16 + tig * 2;
            qf[ks][0] = *(const uint32_t*)&Qg[(size_t)(qb + g    ) * DM + c];
            qf[ks][1] = *(const uint32_t*)&Qg[(size_t)(qb + g + 8) * DM + c];
            qf[ks][2] = *(const uint32_t*)&Qg[(size_t)(qb + g    ) * DM + c + 8];
            qf[ks][3] = *(const uint32_t*)&Qg[(size_t)(qb + g + 8) * DM + c + 8];
        }

        float m0 = -1e30f, m1 = -1e30f, l0 = 0.0f, l1 = 0.0f;
        float O[8][4] = {};

        const int jmax = 2 * qt + 1;

        {
            const char* ksrc = (const char*)&Kg[(size_t)lr * DM] + lcb;
            uint32_t kdst = smem_u32(&Ks[0][lr][0]) + lcb;
            cp16(kdst, ksrc); cp16(kdst + 16, ksrc + 16);
            const char* vsrc = (const char*)&Vg[(size_t)lr * SEQ] + lcb;
            uint32_t vdst = smem_u32(&Vt[0][lr][0]) + lcb;
            cp16(vdst, vsrc); cp16(vdst + 16, vsrc + 16);
            asm volatile("cp.async.commit_group;");
        }

        for (int j = 0; j <= jmax; j++) {
            const int bf = j & 1;
            if (j < jmax) {
                const int jn = j + 1, bn = jn & 1;
                const char* ksrc = (const char*)&Kg[(size_t)(jn * 64 + lr) * DM] + lcb;
                uint32_t kdst = smem_u32(&Ks[bn][lr][0]) + lcb;
                cp16(kdst, ksrc); cp16(kdst + 16, ksrc + 16);
                const char* vsrc = (const char*)&Vg[(size_t)lr * SEQ + jn * 64] + lcb;
                uint32_t vdst = smem_u32(&Vt[bn][lr][0]) + lcb;
                cp16(vdst, vsrc); cp16(vdst + 16, vsrc + 16);
                asm volatile("cp.async.commit_group;");
                asm volatile("cp.async.wait_group 1;");
            } else {
                asm volatile("cp.async.wait_group 0;");
            }
            __syncthreads();

            if (j * 64 <= qb + 15) {
                const uint32_t kb = kbase0 + (uint32_t)bf * 64 * HROWB;
                const uint32_t vb = vbase0 + (uint32_t)bf * 64 * HROWB;

                float S[8][4] = {};
                #pragma unroll
                for (int ks = 0; ks < 4; ks++) {
                    const int kk = ks * 16;
                    #pragma unroll
                    for (int p = 0; p < 4; p++) {
                        uint32_t kf[4];
                        int r = p * 16 + row_in + sel16 * 8;
                        int c = kk + sel8 * 8;
                        ldm_x4(kf, kb + r * HROWB + c * 2);
                        mma_f16_16x8x16(S[2*p    ], qf[ks], kf[0], kf[1]);
                        mma_f16_16x8x16(S[2*p + 1], qf[ks], kf[2], kf[3]);
                    }
                }

                if (j >= 2 * qt) {
                    #pragma unroll
                    for (int nt = 0; nt < 8; nt++) {
                        int colb = j * 64 + nt * 8 + tig * 2;
                        int r0 = qb + g, r1 = qb + g + 8;
                        if (colb     > r0) S[nt][0] = -1e30f;
                        if (colb + 1 > r0) S[nt][1] = -1e30f;
                        if (colb     > r1) S[nt][2] = -1e30f;
                        if (colb + 1 > r1) S[nt][3] = -1e30f;
                    }
                }

                float mx0 = -1e30f, mx1 = -1e30f;
                #pragma unroll
                for (int nt = 0; nt < 8; nt++) {
                    mx0 = fmaxf(mx0, fmaxf(S[nt][0], S[nt][1]));
                    mx1 = fmaxf(mx1, fmaxf(S[nt][2], S[nt][3]));
                }
                mx0 = fmaxf(mx0, __shfl_xor_sync(0xffffffffu, mx0, 1));
                mx0 = fmaxf(mx0, __shfl_xor_sync(0xffffffffu, mx0, 2));
                mx1 = fmaxf(mx1, __shfl_xor_sync(0xffffffffu, mx1, 1));
                mx1 = fmaxf(mx1, __shfl_xor_sync(0xffffffffu, mx1, 2));

                float mn0 = fmaxf(m0, mx0), mn1 = fmaxf(m1, mx1);
                float al0 = exp2f(m0 - mn0), al1 = exp2f(m1 - mn1);

                uint32_t Ph[8][2];
                float s0 = 0.0f, s1 = 0.0f;
                #pragma unroll
                for (int nt = 0; nt < 8; nt++) {
                    Ph[nt][0] = ex2_h2(pack_h2(S[nt][0] - mn0, S[nt][1] - mn0));
                    Ph[nt][1] = ex2_h2(pack_h2(S[nt][2] - mn1, S[nt][3] - mn1));
                    float2 p0 = __half22float2(*(__half2*)&Ph[nt][0]);
                    float2 p1 = __half22float2(*(__half2*)&Ph[nt][1]);
                    s0 += p0.x + p0.y;
                    s1 += p1.x + p1.y;
                }
                s0 += __shfl_xor_sync(0xffffffffu, s0, 1);
                s0 += __shfl_xor_sync(0xffffffffu, s0, 2);
                s1 += __shfl_xor_sync(0xffffffffu, s1, 1);
                s1 += __shfl_xor_sync(0xffffffffu, s1, 2);
                l0 = l0 * al0 + s0;  l1 = l1 * al1 + s1;
                m0 = mn0;            m1 = mn1;

                #pragma unroll
                for (int nt = 0; nt < 8; nt++) {
                    O[nt][0] *= al0; O[nt][1] *= al0;
                    O[nt][2] *= al1; O[nt][3] *= al1;
                }

                #pragma unroll
                for (int ks = 0; ks < 4; ks++) {
                    uint32_t a[4];
                    a[0] = Ph[2*ks    ][0];
                    a[1] = Ph[2*ks    ][1];
                    a[2] = Ph[2*ks + 1][0];
                    a[3] = Ph[2*ks + 1][1];
                    const int kk = ks * 16;
                    #pragma unroll
                    for (int p = 0; p < 4; p++) {
                        uint32_t vf[4];
                        int r = p * 16 + row_in + sel16 * 8;
                        int c = kk + sel8 * 8;
                        ldm_x4(vf, vb + r * HROWB + c * 2);
                        mma_f16_16x8x16(O[2*p    ], a, vf[0], vf[1]);
                        mma_f16_16x8x16(O[2*p + 1], a, vf[2], vf[3]);
                    }
                }
            }
            __syncthreads();
        }

        float inv0 = 1.0f / l0, inv1 = 1.0f / l1;
        #pragma unroll
        for (int nt = 0; nt < 8; nt++) {
            int col = h * DH + nt * 8 + tig * 2;
            int r0 = qb + g, r1 = qb + g + 8;
            *(float2*)&out[(size_t)(b * SEQ + r0) * DM + col] =
                make_float2(O[nt][0] * inv0, O[nt][1] * inv0);
            *(float2*)&out[(size_t)(b * SEQ + r1) * DM + col] =
                make_float2(O[nt][2] * inv1, O[nt][3] * inv1);
        }
    }
}

extern "C" void kernel_launch(void* const* d_in, const int* in_sizes, int n_in,
                              void* d_out, int out_size)
{
    const float* X  = (const float*)d_in[0];
    const float* Wq = (const float*)d_in[1];
    const float* Wk = (const float*)d_in[2];
    const float* Wv = (const float*)d_in[3];
    float* out = (float*)d_out;

    cvt_half<<<(NXF + NWF) / 8 / 256, 256>>>(X, Wq, Wk, Wv);

    dim3 ggrid(DM / 128, MTOT / 128, 3);
    qkv_gemm_h2<<<ggrid, 256>>>();

    dim3 agrid(9, NH, BATCH);
    attn_tc<<<agrid, 256>>>(out);
}

// round 17
// speedup vs baseline: 1.1107x; 1.0111x over previous
#include <cuda_runtime.h>
#include <cuda_fp16.h>
#include <cuda_bf16.h>
#include <cstdint>

#define BATCH 2
#define SEQ   2048
#define DM    1024
#define NH    16
#define DH    64
#define MTOT  (BATCH*SEQ)   // 4096
#define NXF   (MTOT*DM)
#define NWF   (3*DM*DM)

__device__ __half g_Xh[NXF];
__device__ __half g_Wh[NWF];
__device__ __half g_Qh[MTOT*DM];   // [b,t,dm], pre-scaled by log2(e)/8
__device__ __half g_Kh[MTOT*DM];   // [b,t,dm]
__device__ __half g_Vt[MTOT*DM];   // [b, h*64+d, t] (transposed)

__device__ __forceinline__ void mma_f16_16x8x16(float* c, const uint32_t* a, uint32_t b0, uint32_t b1) {
    asm volatile(
        "mma.sync.aligned.m16n8k16.row.col.f32.f16.f16.f32 "
        "{%0,%1,%2,%3}, {%4,%5,%6,%7}, {%8,%9}, {%0,%1,%2,%3};"
        : "+f"(c[0]), "+f"(c[1]), "+f"(c[2]), "+f"(c[3])
        : "r"(a[0]), "r"(a[1]), "r"(a[2]), "r"(a[3]), "r"(b0), "r"(b1));
}

__device__ __forceinline__ void ldm_x4(uint32_t* r, uint32_t addr) {
    asm volatile("ldmatrix.sync.aligned.m8n8.x4.shared.b16 {%0,%1,%2,%3}, [%4];"
        : "=r"(r[0]), "=r"(r[1]), "=r"(r[2]), "=r"(r[3]) : "r"(addr));
}

__device__ __forceinline__ uint32_t pack_h2(float lo, float hi) {
    __half2 h = __floats2half2_rn(lo, hi);
    return *(uint32_t*)&h;
}

__device__ __forceinline__ uint32_t ex2_h2(uint32_t x) {
    uint32_t r;
    asm("ex2.approx.f16x2 %0, %1;" : "=r"(r) : "r"(x));
    return r;
}

__device__ __forceinline__ uint32_t smem_u32(const void* p) {
    return (uint32_t)__cvta_generic_to_shared(p);
}

__device__ __forceinline__ void cp16(uint32_t dst, const void* src) {
    asm volatile("cp.async.cg.shared.global [%0], [%1], 16;" :: "r"(dst), "l"(src));
}

// ---------------------------------------------------------------------------
// Prepass: X, Wq, Wk, Wv -> half.
// ---------------------------------------------------------------------------
__global__ __launch_bounds__(256) void cvt_half(
    const float* __restrict__ X,  const float* __restrict__ Wq,
    const float* __restrict__ Wk, const float* __restrict__ Wv)
{
    size_t i8 = ((size_t)blockIdx.x * 256 + threadIdx.x) * 8;
    const float* src;
    __half* dst;
    if (i8 < NXF) {
        src = X + i8;  dst = g_Xh + i8;
    } else {
        size_t j = i8 - NXF;
        size_t w = j / (DM * DM);
        size_t o = j - w * (DM * DM);
        src = ((w == 0) ? Wq : (w == 1) ? Wk : Wv) + o;
        dst = g_Wh + j;
    }
    float4 a = *(const float4*)src;
    float4 b = *(const float4*)(src + 4);
    uint4 o4;
    o4.x = pack_h2(a.x, a.y); o4.y = pack_h2(a.z, a.w);
    o4.z = pack_h2(b.x, b.y); o4.w = pack_h2(b.z, b.w);
    *(uint4*)dst = o4;
}

// ---------------------------------------------------------------------------
// QKV projection: fp16 mma + ldmatrix, 2-stage cp.async, occ=2  (R14 exact).
// ---------------------------------------------------------------------------
#define KC    32
#define XSTR  20
#define GROWB 80          // bytes per smem row
#define TSTR  136         // halves per transpose row

__global__ __launch_bounds__(256, 2) void qkv_gemm_h2()
{
    __shared__ __align__(16) char sbuf[40960];
    uint32_t (*Xs)[128][XSTR] = (uint32_t (*)[128][XSTR])sbuf;
    uint32_t (*Ws)[128][XSTR] = (uint32_t (*)[128][XSTR])(sbuf + 20480);

    const int z = blockIdx.z;
    const __half* Wsrc = g_Wh + (size_t)z * DM * DM;

    const int m0 = blockIdx.y * 128;
    const int n0 = blockIdx.x * 128;
    const int tid  = threadIdx.x;
    const int wid  = tid >> 5;
    const int lane = tid & 31;
    const int wm = wid >> 2;
    const int wn = wid & 3;
    const int g   = lane >> 2;
    const int tig = lane & 3;

    const int row_in = lane & 7;
    const int sel8   = (lane >> 3) & 1;
    const int sel16  = lane >> 4;

    const int qr  = tid >> 1;
    const int qcb = (tid & 1) * 32;

    const __half* xrow = &g_Xh[(size_t)(m0 + qr) * DM];
    const __half* wrow = &Wsrc[(size_t)(n0 + qr) * DM];

    {
        const char* xs = (const char*)(xrow) + qcb;
        uint32_t xd = smem_u32(&Xs[0][qr][0]) + qcb;
        cp16(xd, xs); cp16(xd + 16, xs + 16);
        const char* ws = (const char*)(wrow) + qcb;
        uint32_t wd = smem_u32(&Ws[0][qr][0]) + qcb;
        cp16(wd, ws); cp16(wd + 16, ws + 16);
        asm volatile("cp.async.commit_group;");
    }

    float acc[4][4][4] = {};

    const uint32_t xbase0 = smem_u32(&Xs[0][0][0]);
    const uint32_t wbase0 = smem_u32(&Ws[0][0][0]);

    for (int kc = 0; kc < DM / KC; kc++) {
        asm volatile("cp.async.wait_group 0;");
        __syncthreads();

        if (kc < DM / KC - 1) {
            const int bn = (kc + 1) & 1;
            const char* xs = (const char*)(xrow + (kc + 1) * KC) + qcb;
            uint32_t xd = smem_u32(&Xs[bn][qr][0]) + qcb;
            cp16(xd, xs); cp16(xd + 16, xs + 16);
            const char* ws = (const char*)(wrow + (kc + 1) * KC) + qcb;
            uint32_t wd = smem_u32(&Ws[bn][qr][0]) + qcb;
            cp16(wd, ws); cp16(wd + 16, ws + 16);
            asm volatile("cp.async.commit_group;");
        }

        const int bf = kc & 1;
        const uint32_t xb = xbase0 + (uint32_t)bf * 128 * GROWB;
        const uint32_t wb = wbase0 + (uint32_t)bf * 128 * GROWB;

        #pragma unroll
        for (int ks = 0; ks < 2; ks++) {
            const int kk = ks * 16;
            uint32_t a[4][4];
            #pragma unroll
            for (int mt = 0; mt < 4; mt++) {
                int r = wm * 64 + mt * 16 + row_in + sel8 * 8;
                int c = kk + sel16 * 8;
                ldm_x4(a[mt], xb + r * GROWB + c * 2);
            }
            uint32_t b[2][4];
            #pragma unroll
            for (int p = 0; p < 2; p++) {
                int r = wn * 32 + p * 16 + row_in + sel16 * 8;
                int c = kk + sel8 * 8;
                ldm_x4(b[p], wb + r * GROWB + c * 2);
            }
            #pragma unroll
            for (int mt = 0; mt < 4; mt++) {
                mma_f16_16x8x16(acc[mt][0], a[mt], b[0][0], b[0][1]);
                mma_f16_16x8x16(acc[mt][1], a[mt], b[0][2], b[0][3]);
                mma_f16_16x8x16(acc[mt][2], a[mt], b[1][0], b[1][1]);
                mma_f16_16x8x16(acc[mt][3], a[mt], b[1][2], b[1][3]);
            }
        }
    }

    if (z == 0) {
        const float s = 0.125f * 1.4426950408889634f;   // fold log2(e): exp2-domain softmax
        #pragma unroll
        for (int mt = 0; mt < 4; mt++) {
            int row = m0 + wm * 64 + mt * 16 + g;
            #pragma unroll
            for (int nt = 0; nt < 4; nt++) {
                int col = n0 + wn * 32 + nt * 8 + tig * 2;
                *(uint32_t*)&g_Qh[(size_t)row * DM + col] =
                    pack_h2(acc[mt][nt][0] * s, acc[mt][nt][1] * s);
                *(uint32_t*)&g_Qh[(size_t)(row + 8) * DM + col] =
                    pack_h2(acc[mt][nt][2] * s, acc[mt][nt][3] * s);
            }
        }
    } else if (z == 1) {
        #pragma unroll
        for (int mt = 0; mt < 4; mt++) {
            int row = m0 + wm * 64 + mt * 16 + g;
            #pragma unroll
            for (int nt = 0; nt < 4; nt++) {
                int col = n0 + wn * 32 + nt * 8 + tig * 2;
                *(uint32_t*)&g_Kh[(size_t)row * DM + col] =
                    pack_h2(acc[mt][nt][0], acc[mt][nt][1]);
                *(uint32_t*)&g_Kh[(size_t)(row + 8) * DM + col] =
                    pack_h2(acc[mt][nt][2], acc[mt][nt][3]);
            }
        }
    } else {
        __syncthreads();
        __half* Tr = (__half*)sbuf;      // [128 cols][TSTR]
        #pragma unroll
        for (int mt = 0; mt < 4; mt++) {
            int rl = wm * 64 + mt * 16 + g;
            #pragma unroll
            for (int nt = 0; nt < 4; nt++) {
                int cl = wn * 32 + nt * 8 + tig * 2;
                Tr[(cl    ) * TSTR + rl    ] = __float2half(acc[mt][nt][0]);
                Tr[(cl + 1) * TSTR + rl    ] = __float2half(acc[mt][nt][1]);
                Tr[(cl    ) * TSTR + rl + 8] = __float2half(acc[mt][nt][2]);
                Tr[(cl + 1) * TSTR + rl + 8] = __float2half(acc[mt][nt][3]);
            }
        }
        __syncthreads();
        const int bz = m0 >> 11;
        const int t0 = m0 & (SEQ - 1);
        const int cn  = tid >> 1;
        const int off = (tid & 1) * 64;
        __half* dst = &g_Vt[((size_t)bz * DM + n0 + cn) * SEQ + t0 + off];
        const __half* srow = &Tr[cn * TSTR + off];
        #pragma unroll
        for (int q = 0; q < 8; q++)
            *(uint4*)(dst + q * 8) = *(const uint4*)(srow + q * 8);
    }
}

// ---------------------------------------------------------------------------
// Tensor-core flash attention. Balanced 9-group schedule (R16) + single-sync
// pipeline: wait -> sync -> prefetch(j+1) -> compute. One barrier per tile.
// ---------------------------------------------------------------------------
#define HSTR  72
#define HROWB 144
#define NQT  (SEQ / 128)

__global__ __launch_bounds__(256, 2) void attn_tc(float* __restrict__ out)
{
    const int qa = blockIdx.x;   // 0..8
    const int h  = blockIdx.y;
    const int b  = blockIdx.z;

    __shared__ __half Ks[2][64][HSTR];
    __shared__ __half Vt[2][64][HSTR];

    const int tid  = threadIdx.x;
    const int w    = tid >> 5;
    const int lane = tid & 31;
    const int g    = lane >> 2;
    const int tig  = lane & 3;
    const int row_in = lane & 7;
    const int sel8   = (lane >> 3) & 1;
    const int sel16  = lane >> 4;

    const __half* Qg = g_Qh + (size_t)b * SEQ * DM + h * DH;
    const __half* Kg = g_Kh + (size_t)b * SEQ * DM + h * DH;
    const __half* Vg = g_Vt + ((size_t)b * DM + h * DH) * SEQ;

    const int lr  = tid >> 2;
    const int lcb = (tid & 3) * 32;

    const uint32_t kbase0 = smem_u32(&Ks[0][0][0]);
    const uint32_t vbase0 = smem_u32(&Vt[0][0][0]);

    // balanced groups: heavy tile first within each group
    int qts[2];
    int nq;
    if (qa == 0)      { qts[0] = 15;      nq = 1; }
    else if (qa == 8) { qts[0] = 7;       nq = 1; }
    else              { qts[0] = 15 - qa; qts[1] = qa - 1; nq = 2; }

    #pragma unroll 1
    for (int iq = 0; iq < nq; iq++) {
        const int qt = qts[iq];
        const int qb = qt * 128 + w * 16;

        uint32_t qf[4][4];
        #pragma unroll
        for (int ks = 0; ks < 4; ks++) {
            int c = ks * 16 + tig * 2;
            qf[ks][0] = *(const uint32_t*)&Qg[(size_t)(qb + g    ) * DM + c];
            qf[ks][1] = *(const uint32_t*)&Qg[(size_t)(qb + g + 8) * DM + c];
            qf[ks][2] = *(const uint32_t*)&Qg[(size_t)(qb + g    ) * DM + c + 8];
            qf[ks][3] = *(const uint32_t*)&Qg[(size_t)(qb + g + 8) * DM + c + 8];
        }

        float m0 = -1e30f, m1 = -1e30f, l0 = 0.0f, l1 = 0.0f;
        float O[8][4] = {};

        const int jmax = 2 * qt + 1;

        // prologue: tile 0 -> buffer 0 (safe: prior iq fully drained both
        // buffers before any thread could exit its last top-barrier)
        {
            const char* ksrc = (const char*)&Kg[(size_t)lr * DM] + lcb;
            uint32_t kdst = smem_u32(&Ks[0][lr][0]) + lcb;
            cp16(kdst, ksrc); cp16(kdst + 16, ksrc + 16);
            const char* vsrc = (const char*)&Vg[(size_t)lr * SEQ] + lcb;
            uint32_t vdst = smem_u32(&Vt[0][lr][0]) + lcb;
            cp16(vdst, vsrc); cp16(vdst + 16, vsrc + 16);
            asm volatile("cp.async.commit_group;");
        }

        for (int j = 0; j <= jmax; j++) {
            const int bf = j & 1;

            asm volatile("cp.async.wait_group 0;");   // tile j landed
            __syncthreads();                           // all done reading buf (j+1)&1 from iter j-1

            if (j < jmax) {                            // prefetch j+1 AFTER the barrier
                const int jn = j + 1, bn = jn & 1;
                const char* ksrc = (const char*)&Kg[(size_t)(jn * 64 + lr) * DM] + lcb;
                uint32_t kdst = smem_u32(&Ks[bn][lr][0]) + lcb;
                cp16(kdst, ksrc); cp16(kdst + 16, ksrc + 16);
                const char* vsrc = (const char*)&Vg[(size_t)lr * SEQ + jn * 64] + lcb;
                uint32_t vdst = smem_u32(&Vt[bn][lr][0]) + lcb;
                cp16(vdst, vsrc); cp16(vdst + 16, vsrc + 16);
                asm volatile("cp.async.commit_group;");
            }

            if (j * 64 <= qb + 15) {
                const uint32_t kb = kbase0 + (uint32_t)bf * 64 * HROWB;
                const uint32_t vb = vbase0 + (uint32_t)bf * 64 * HROWB;

                float S[8][4] = {};
                #pragma unroll
                for (int ks = 0; ks < 4; ks++) {
                    const int kk = ks * 16;
                    #pragma unroll
                    for (int p = 0; p < 4; p++) {
                        uint32_t kf[4];
                        int r = p * 16 + row_in + sel16 * 8;
                        int c = kk + sel8 * 8;
                        ldm_x4(kf, kb + r * HROWB + c * 2);
                        mma_f16_16x8x16(S[2*p    ], qf[ks], kf[0], kf[1]);
                        mma_f16_16x8x16(S[2*p + 1], qf[ks], kf[2], kf[3]);
                    }
                }

                if (j >= 2 * qt) {
                    #pragma unroll
                    for (int nt = 0; nt < 8; nt++) {
                        int colb = j * 64 + nt * 8 + tig * 2;
                        int r0 = qb + g, r1 = qb + g + 8;
                        if (colb     > r0) S[nt][0] = -1e30f;
                        if (colb + 1 > r0) S[nt][1] = -1e30f;
                        if (colb     > r1) S[nt][2] = -1e30f;
                        if (colb + 1 > r1) S[nt][3] = -1e30f;
                    }
                }

                float mx0 = -1e30f, mx1 = -1e30f;
                #pragma unroll
                for (int nt = 0; nt < 8; nt++) {
                    mx0 = fmaxf(mx0, fmaxf(S[nt][0], S[nt][1]));
                    mx1 = fmaxf(mx1, fmaxf(S[nt][2], S[nt][3]));
                }
                mx0 = fmaxf(mx0, __shfl_xor_sync(0xffffffffu, mx0, 1));
                mx0 = fmaxf(mx0, __shfl_xor_sync(0xffffffffu, mx0, 2));
                mx1 = fmaxf(mx1, __shfl_xor_sync(0xffffffffu, mx1, 1));
                mx1 = fmaxf(mx1, __shfl_xor_sync(0xffffffffu, mx1, 2));

                float mn0 = fmaxf(m0, mx0), mn1 = fmaxf(m1, mx1);
                float al0 = exp2f(m0 - mn0), al1 = exp2f(m1 - mn1);

                uint32_t Ph[8][2];
                float s0 = 0.0f, s1 = 0.0f;
                #pragma unroll
                for (int nt = 0; nt < 8; nt++) {
                    Ph[nt][0] = ex2_h2(pack_h2(S[nt][0] - mn0, S[nt][1] - mn0));
                    Ph[nt][1] = ex2_h2(pack_h2(S[nt][2] - mn1, S[nt][3] - mn1));
                    float2 p0 = __half22float2(*(__half2*)&Ph[nt][0]);
                    float2 p1 = __half22float2(*(__half2*)&Ph[nt][1]);
                    s0 += p0.x + p0.y;
                    s1 += p1.x + p1.y;
                }
                s0 += __shfl_xor_sync(0xffffffffu, s0, 1);
                s0 += __shfl_xor_sync(0xffffffffu, s0, 2);
                s1 += __shfl_xor_sync(0xffffffffu, s1, 1);
                s1 += __shfl_xor_sync(0xffffffffu, s1, 2);
                l0 = l0 * al0 + s0;  l1 = l1 * al1 + s1;
                m0 = mn0;            m1 = mn1;

                #pragma unroll
                for (int nt = 0; nt < 8; nt++) {
                    O[nt][0] *= al0; O[nt][1] *= al0;
                    O[nt][2] *= al1; O[nt][3] *= al1;
                }

                #pragma unroll
                for (int ks = 0; ks < 4; ks++) {
                    uint32_t a[4];
                    a[0] = Ph[2*ks    ][0];
                    a[1] = Ph[2*ks    ][1];
                    a[2] = Ph[2*ks + 1][0];
                    a[3] = Ph[2*ks + 1][1];
                    const int kk = ks * 16;
                    #pragma unroll
                    for (int p = 0; p < 4; p++) {
                        uint32_t vf[4];
                        int r = p * 16 + row_in + sel16 * 8;
                        int c = kk + sel8 * 8;
                        ldm_x4(vf, vb + r * HROWB + c * 2);
                        mma_f16_16x8x16(O[2*p    ], a, vf[0], vf[1]);
                        mma_f16_16x8x16(O[2*p + 1], a, vf[2], vf[3]);
                    }
                }
            }
        }

        float inv0 = 1.0f / l0, inv1 = 1.0f / l1;
        #pragma unroll
        for (int nt = 0; nt < 8; nt++) {
            int col = h * DH + nt * 8 + tig * 2;
            int r0 = qb + g, r1 = qb + g + 8;
            *(float2*)&out[(size_t)(b * SEQ + r0) * DM + col] =
                make_float2(O[nt][0] * inv0, O[nt][1] * inv0);
            *(float2*)&out[(size_t)(b * SEQ + r1) * DM + col] =
                make_float2(O[nt][2] * inv1, O[nt][3] * inv1);
        }
    }
}

extern "C" void kernel_launch(void* const* d_in, const int* in_sizes, int n_in,
                              void* d_out, int out_size)
{
    const float* X  = (const float*)d_in[0];
    const float* Wq = (const float*)d_in[1];
    const float* Wk = (const float*)d_in[2];
    const float* Wv = (const float*)d_in[3];
    float* out = (float*)d_out;

    cvt_half<<<(NXF + NWF) / 8 / 256, 256>>>(X, Wq, Wk, Wv);

    dim3 ggrid(DM / 128, MTOT / 128, 3);
    qkv_gemm_h2<<<ggrid, 256>>>();

    dim3 agrid(9, NH, BATCH);
    attn_tc<<<agrid, 256>>>(out);
}